// round 12
// baseline (speedup 1.0000x reference)
#include <cuda_runtime.h>
#include <cuda_fp16.h>
#include <cstdint>

// ---------------- problem constants ----------------
#define NTOK   16384
#define DDIM   512
#define HDIM   1408
#define NEXP   8
#define KTOP   2
#define NPAIR  (NTOK*KTOP)
#define MTILE  128
#define MAX_MT 264

// ---------------- device scratch ----------------
__device__ __half g_xh [(size_t)NTOK * DDIM];
__device__ __half g_w1h[(size_t)NEXP * HDIM * DDIM];
__device__ __half g_w3h[(size_t)NEXP * HDIM * DDIM];
__device__ __half g_w2h[(size_t)NEXP * DDIM * HDIM];
__device__ __half g_h  [(size_t)NPAIR * HDIM];
__device__ float  g_y  [(size_t)NPAIR * DDIM];
__device__ int    g_tok_of_pair[NPAIR];
__device__ int    g_slot[NTOK * KTOP];
__device__ int    g_exp_of_tok[NTOK * KTOP];
__device__ float  g_wt_of_tok[NTOK * KTOP];
__device__ int    g_counts[NEXP];
__device__ int    g_cursor[NEXP];
__device__ int    g_offsets[NEXP + 1];
__device__ float  g_usage[NEXP];
__device__ int    g_tile_expert[MAX_MT];
__device__ int    g_tile_row[MAX_MT];
__device__ int    g_ntiles;

// ---------------- helpers ----------------
__device__ __forceinline__ uint32_t smem_u32(const void* p) {
    uint32_t a;
    asm("{ .reg .u64 t; cvta.to.shared.u64 t, %1; cvt.u32.u64 %0, t; }" : "=r"(a) : "l"(p));
    return a;
}
__device__ __forceinline__ void cp16(uint32_t dst, const void* src) {
    asm volatile("cp.async.cg.shared.global [%0], [%1], 16;" :: "r"(dst), "l"(src));
}
#define CP_COMMIT() asm volatile("cp.async.commit_group;" ::: "memory")
#define CP_WAIT1()  asm volatile("cp.async.wait_group 1;" ::: "memory")
#define SWZ(x) ((x) ^ (((x) >> 3) & 0x70))

#define LDSM4(r0, r1, r2, r3, addr) \
    asm volatile("ldmatrix.sync.aligned.m8n8.x4.shared.b16 {%0,%1,%2,%3}, [%4];" \
        : "=r"(r0), "=r"(r1), "=r"(r2), "=r"(r3) : "r"(addr))

__device__ __forceinline__ void mma_f16(float* c, const uint32_t* a, const uint32_t* b) {
    asm volatile(
        "mma.sync.aligned.m16n8k16.row.col.f32.f16.f16.f32 "
        "{%0,%1,%2,%3}, {%4,%5,%6,%7}, {%8,%9}, {%0,%1,%2,%3};\n"
        : "+f"(c[0]), "+f"(c[1]), "+f"(c[2]), "+f"(c[3])
        : "r"(a[0]), "r"(a[1]), "r"(a[2]), "r"(a[3]), "r"(b[0]), "r"(b[1]));
}

// ---------------- small kernels (verified) ----------------
__global__ void init_kernel() {
    int i = threadIdx.x;
    if (i < NEXP) { g_counts[i] = 0; g_cursor[i] = 0; g_usage[i] = 0.f; }
}

__global__ void __launch_bounds__(256) router_kernel(const float* __restrict__ x,
                                                     const float* __restrict__ rw) {
    int warp = threadIdx.x >> 5, lane = threadIdx.x & 31;
    int tok = blockIdx.x * 8 + warp;
    if (tok >= NTOK) return;
    const float* xr = x + (size_t)tok * DDIM;
    float xv[16];
#pragma unroll
    for (int i = 0; i < 16; i++) xv[i] = xr[lane + 32 * i];
    float logits[NEXP];
#pragma unroll
    for (int e = 0; e < NEXP; e++) {
        const float* wr = rw + e * DDIM;
        float s = 0.f;
#pragma unroll
        for (int i = 0; i < 16; i++) s += xv[i] * wr[lane + 32 * i];
#pragma unroll
        for (int o = 16; o > 0; o >>= 1) s += __shfl_xor_sync(0xffffffffu, s, o);
        logits[e] = s;
    }
    if (lane == 0) {
        float m = logits[0];
#pragma unroll
        for (int e = 1; e < NEXP; e++) m = fmaxf(m, logits[e]);
        float p[NEXP], Z = 0.f;
#pragma unroll
        for (int e = 0; e < NEXP; e++) { p[e] = __expf(logits[e] - m); Z += p[e]; }
        float inv = 1.f / Z;
        int a = 0;
#pragma unroll
        for (int e = 1; e < NEXP; e++) if (p[e] > p[a]) a = e;
        int b = (a == 0) ? 1 : 0;
#pragma unroll
        for (int e = 0; e < NEXP; e++) { if (e == a) continue; if (p[e] > p[b]) b = e; }
        float pa = p[a] * inv, pb = p[b] * inv, ws = pa + pb;
        g_exp_of_tok[tok * 2 + 0] = a;
        g_exp_of_tok[tok * 2 + 1] = b;
        g_wt_of_tok[tok * 2 + 0] = pa / ws;
        g_wt_of_tok[tok * 2 + 1] = pb / ws;
        atomicAdd(&g_counts[a], 1);
        atomicAdd(&g_counts[b], 1);
#pragma unroll
        for (int e = 0; e < NEXP; e++) atomicAdd(&g_usage[e], p[e] * inv);
    }
}

__global__ void scan_kernel() {
    if (threadIdx.x != 0) return;
    int off = 0;
    for (int e = 0; e < NEXP; e++) { g_offsets[e] = off; off += g_counts[e]; }
    g_offsets[NEXP] = off;
    int nt = 0;
    for (int e = 0; e < NEXP; e++) {
        int cnt = g_counts[e];
        for (int r = 0; r < cnt; r += MTILE) {
            g_tile_expert[nt] = e;
            g_tile_row[nt] = g_offsets[e] + r;
            nt++;
        }
    }
    g_ntiles = nt;
}

__global__ void build_kernel() {
    int i = blockIdx.x * blockDim.x + threadIdx.x;
    if (i >= NTOK * KTOP) return;
    int e = g_exp_of_tok[i];
    int pos = g_offsets[e] + atomicAdd(&g_cursor[e], 1);
    g_tok_of_pair[pos] = i >> 1;
    g_slot[i] = pos;
}

__global__ void cvt_kernel(const float4* __restrict__ src, uint4* __restrict__ dst, int n8) {
    int i = blockIdx.x * blockDim.x + threadIdx.x;
    if (i >= n8) return;
    float4 s0 = src[2 * i], s1 = src[2 * i + 1];
    __half2 h0 = __floats2half2_rn(s0.x, s0.y);
    __half2 h1 = __floats2half2_rn(s0.z, s0.w);
    __half2 h2 = __floats2half2_rn(s1.x, s1.y);
    __half2 h3 = __floats2half2_rn(s1.z, s1.w);
    uint4 o;
    o.x = *(uint32_t*)&h0; o.y = *(uint32_t*)&h1;
    o.z = *(uint32_t*)&h2; o.w = *(uint32_t*)&h3;
    dst[i] = o;
}

// ============================================================
// GEMM config: CTA 128M, BK=64 fp16 (128B rows), 3-stage cp.async,
// SW128 swizzle, ldmatrix b16, m16n8k16 mma.
// 128 threads/CTA, warp tile 64x64 (4 warps), 2 CTAs/SM.
// Stage: A [128 x 128B] @0, B [128 x 128B] @16K. 96 KB total.
// ============================================================
#define BK        64
#define NSTG      3
#define STG_BYTES 32768
#define BOFF      16384
#define GSMEM     (NSTG * STG_BYTES)

// ---------------- GEMM1: h = silu(x@w1^T)*(x@w3^T) ----------------
// CTA 128M x 64N per matrix; B smem rows 0-63 = w1, 64-127 = w3.
// 4 warps: 2(M) x 2(N); warp = 64M x 32N dual.
__global__ void __launch_bounds__(128, 2) gemm1_mm() {
    extern __shared__ char smem[];
    int mt = blockIdx.y;
    if (mt >= g_ntiles) return;
    int e = g_tile_expert[mt];
    int row0 = g_tile_row[mt];
    int valid = g_offsets[e + 1] - row0; if (valid > MTILE) valid = MTILE;
    int n0 = blockIdx.x * 64;

    uint32_t sb = smem_u32(smem);
    int tid = threadIdx.x;

    // loaders: thread -> one full A row + one full B row (8 cp16 each)
    int aidx = row0 + tid; if (aidx >= NPAIR) aidx = NPAIR - 1;
    const __half* asrc = g_xh + (size_t)g_tok_of_pair[aidx] * DDIM;
    const __half* bsrc = (tid < 64)
        ? g_w1h + (size_t)e * HDIM * DDIM + (size_t)(n0 + tid) * DDIM
        : g_w3h + (size_t)e * HDIM * DDIM + (size_t)(n0 + tid - 64) * DDIM;
    uint32_t abase = tid * 128;

#define G1_LD(kc, st) do { \
    uint32_t _s = sb + (st) * STG_BYTES; \
    const __half* _a = asrc + (kc) * BK; \
    const __half* _b = bsrc + (kc) * BK; \
    _Pragma("unroll") for (int c = 0; c < 8; c++) { \
        cp16(_s + SWZ(abase + c * 16), _a + c * 8); \
        cp16(_s + BOFF + SWZ(abase + c * 16), _b + c * 8); \
    } \
    CP_COMMIT(); \
} while (0)

    int w = tid >> 5, lane = tid & 31;
    int wm = (w & 1) * 64, wn = (w >> 1) * 32;
    int l7 = lane & 7;
    int rA = l7 + ((lane >> 3) & 1) * 8;
    int cA = ((lane >> 4) & 1) * 16;
    int rB = l7 + ((lane >> 4) & 1) * 8;
    int cB = ((lane >> 3) & 1) * 16;
    int gid = lane >> 2, tig = lane & 3;

    float acc1[4][4][4] = {}, acc3[4][4][4] = {};

    G1_LD(0, 0);
    G1_LD(1, 1);
    const int NC = DDIM / BK;   // 8
    for (int kc = 0; kc < NC; kc++) {
        int st = kc % NSTG;
        CP_WAIT1();
        __syncthreads();
        if (kc + 2 < NC) G1_LD(kc + 2, (kc + 2) % NSTG); else CP_COMMIT();

        uint32_t sA = sb + st * STG_BYTES;
        uint32_t sB = sA + BOFF;
#pragma unroll
        for (int kk = 0; kk < 4; kk++) {
            uint32_t a[4][4];
#pragma unroll
            for (int mi = 0; mi < 4; mi++)
                LDSM4(a[mi][0], a[mi][1], a[mi][2], a[mi][3],
                      sA + SWZ((wm + mi * 16 + rA) * 128 + kk * 32 + cA));
            uint32_t b1[2][4], b3[2][4];
#pragma unroll
            for (int ng = 0; ng < 2; ng++) {
                LDSM4(b1[ng][0], b1[ng][1], b1[ng][2], b1[ng][3],
                      sB + SWZ((wn + ng * 16 + rB) * 128 + kk * 32 + cB));
                LDSM4(b3[ng][0], b3[ng][1], b3[ng][2], b3[ng][3],
                      sB + SWZ((64 + wn + ng * 16 + rB) * 128 + kk * 32 + cB));
            }
#pragma unroll
            for (int mi = 0; mi < 4; mi++)
#pragma unroll
                for (int ng = 0; ng < 2; ng++)
#pragma unroll
                    for (int j = 0; j < 2; j++) {
                        mma_f16(acc1[mi][ng * 2 + j], a[mi], &b1[ng][j * 2]);
                        mma_f16(acc3[mi][ng * 2 + j], a[mi], &b3[ng][j * 2]);
                    }
        }
    }

    // epilogue: h = fp16(silu(acc1) * acc3)
#pragma unroll
    for (int mi = 0; mi < 4; mi++)
#pragma unroll
        for (int no = 0; no < 4; no++) {
            int col = n0 + wn + no * 8 + 2 * tig;
#pragma unroll
            for (int hf = 0; hf < 2; hf++) {
                int r = wm + mi * 16 + gid + hf * 8;
                if (r < valid) {
                    float z0 = acc1[mi][no][hf * 2 + 0];
                    float z1 = acc1[mi][no][hf * 2 + 1];
                    float s0 = z0 / (1.f + __expf(-z0));
                    float s1 = z1 / (1.f + __expf(-z1));
                    __half2 v = __floats2half2_rn(s0 * acc3[mi][no][hf * 2 + 0],
                                                  s1 * acc3[mi][no][hf * 2 + 1]);
                    *(__half2*)(g_h + (size_t)(row0 + r) * HDIM + col) = v;
                }
            }
        }
}

// ---------------- GEMM2: y = h @ w2^T ----------------
// CTA 128M x 128N; 4 warps 2(M) x 2(N); warp 64M x 64N; K=1408.
__global__ void __launch_bounds__(128, 2) gemm2_mm() {
    extern __shared__ char smem[];
    int mt = blockIdx.y;
    if (mt >= g_ntiles) return;
    int e = g_tile_expert[mt];
    int row0 = g_tile_row[mt];
    int valid = g_offsets[e + 1] - row0; if (valid > MTILE) valid = MTILE;
    int n0 = blockIdx.x * 128;

    uint32_t sb = smem_u32(smem);
    int tid = threadIdx.x;

    int aidx = row0 + tid; if (aidx >= NPAIR) aidx = NPAIR - 1;
    const __half* asrc = g_h + (size_t)aidx * HDIM;
    const __half* bsrc = g_w2h + (size_t)e * DDIM * HDIM + (size_t)(n0 + tid) * HDIM;
    uint32_t abase = tid * 128;

#define G2_LD(kc, st) do { \
    uint32_t _s = sb + (st) * STG_BYTES; \
    const __half* _a = asrc + (kc) * BK; \
    const __half* _b = bsrc + (kc) * BK; \
    _Pragma("unroll") for (int c = 0; c < 8; c++) { \
        cp16(_s + SWZ(abase + c * 16), _a + c * 8); \
        cp16(_s + BOFF + SWZ(abase + c * 16), _b + c * 8); \
    } \
    CP_COMMIT(); \
} while (0)

    int w = tid >> 5, lane = tid & 31;
    int wm = (w & 1) * 64, wn = (w >> 1) * 64;
    int l7 = lane & 7;
    int rA = l7 + ((lane >> 3) & 1) * 8;
    int cA = ((lane >> 4) & 1) * 16;
    int rB = l7 + ((lane >> 4) & 1) * 8;
    int cB = ((lane >> 3) & 1) * 16;
    int gid = lane >> 2, tig = lane & 3;

    float acc[4][8][4] = {};

    G2_LD(0, 0);
    G2_LD(1, 1);
    const int NC = HDIM / BK;   // 22
    for (int kc = 0; kc < NC; kc++) {
        int st = kc % NSTG;
        CP_WAIT1();
        __syncthreads();
        if (kc + 2 < NC) G2_LD(kc + 2, (kc + 2) % NSTG); else CP_COMMIT();

        uint32_t sA = sb + st * STG_BYTES;
        uint32_t sB = sA + BOFF;
#pragma unroll
        for (int kk = 0; kk < 4; kk++) {
            uint32_t a[4][4];
#pragma unroll
            for (int mi = 0; mi < 4; mi++)
                LDSM4(a[mi][0], a[mi][1], a[mi][2], a[mi][3],
                      sA + SWZ((wm + mi * 16 + rA) * 128 + kk * 32 + cA));
            uint32_t b[4][4];
#pragma unroll
            for (int ng = 0; ng < 4; ng++)
                LDSM4(b[ng][0], b[ng][1], b[ng][2], b[ng][3],
                      sB + SWZ((wn + ng * 16 + rB) * 128 + kk * 32 + cB));
#pragma unroll
            for (int mi = 0; mi < 4; mi++)
#pragma unroll
                for (int ng = 0; ng < 4; ng++)
#pragma unroll
                    for (int j = 0; j < 2; j++)
                        mma_f16(acc[mi][ng * 2 + j], a[mi], &b[ng][j * 2]);
        }
    }

#pragma unroll
    for (int mi = 0; mi < 4; mi++)
#pragma unroll
        for (int no = 0; no < 8; no++) {
            int col = n0 + wn + no * 8 + 2 * tig;
#pragma unroll
            for (int hf = 0; hf < 2; hf++) {
                int r = wm + mi * 16 + gid + hf * 8;
                if (r < valid) {
                    float2 v;
                    v.x = acc[mi][no][hf * 2 + 0];
                    v.y = acc[mi][no][hf * 2 + 1];
                    *(float2*)(g_y + (size_t)(row0 + r) * DDIM + col) = v;
                }
            }
        }
}

// ---------------- combine + aux ----------------
__global__ void combine_kernel(float* __restrict__ out) {
    int i = blockIdx.x * blockDim.x + threadIdx.x;
    const int D4 = DDIM / 4;
    if (i >= NTOK * D4) return;
    int tok = i / D4;
    int d4 = i - tok * D4;
    int s0 = g_slot[tok * 2 + 0], s1 = g_slot[tok * 2 + 1];
    float w0 = g_wt_of_tok[tok * 2 + 0], w1 = g_wt_of_tok[tok * 2 + 1];
    const float4* y4 = (const float4*)g_y;
    float4 a = y4[(size_t)s0 * D4 + d4];
    float4 b = y4[(size_t)s1 * D4 + d4];
    float4 r;
    r.x = w0 * a.x + w1 * b.x;
    r.y = w0 * a.y + w1 * b.y;
    r.z = w0 * a.z + w1 * b.z;
    r.w = w0 * a.w + w1 * b.w;
    ((float4*)out)[i] = r;
}

__global__ void finalize_kernel(float* __restrict__ out, int out_size) {
    if (threadIdx.x != 0 || blockIdx.x != 0) return;
    if (out_size > NTOK * DDIM) {
        float s = 0.f;
        for (int e = 0; e < NEXP; e++) {
            float u = g_usage[e] / (float)NTOK;
            s += u * u;
        }
        out[NTOK * DDIM] = (float)NEXP * 0.01f * s;
    }
}

// ---------------- launch ----------------
extern "C" void kernel_launch(void* const* d_in, const int* in_sizes, int n_in,
                              void* d_out, int out_size) {
    const float* x  = (const float*)d_in[0];
    const float* rw = (const float*)d_in[1];
    const float* w1 = (const float*)d_in[2];
    const float* w2 = (const float*)d_in[3];
    const float* w3 = (const float*)d_in[4];
    float* out = (float*)d_out;

    cudaFuncSetAttribute(gemm1_mm, cudaFuncAttributeMaxDynamicSharedMemorySize, GSMEM);
    cudaFuncSetAttribute(gemm2_mm, cudaFuncAttributeMaxDynamicSharedMemorySize, GSMEM);

    __half* gxh;  cudaGetSymbolAddress((void**)&gxh,  g_xh);
    __half* gw1;  cudaGetSymbolAddress((void**)&gw1,  g_w1h);
    __half* gw3;  cudaGetSymbolAddress((void**)&gw3,  g_w3h);
    __half* gw2;  cudaGetSymbolAddress((void**)&gw2,  g_w2h);

    init_kernel<<<1, 32>>>();
    router_kernel<<<NTOK / 8, 256>>>(x, rw);
    scan_kernel<<<1, 32>>>();
    build_kernel<<<(NTOK * KTOP + 255) / 256, 256>>>();

    int nx8 = NTOK * DDIM / 8, nw8 = NEXP * HDIM * DDIM / 8;
    cvt_kernel<<<(nx8 + 255) / 256, 256>>>((const float4*)x,  (uint4*)gxh, nx8);
    cvt_kernel<<<(nw8 + 255) / 256, 256>>>((const float4*)w1, (uint4*)gw1, nw8);
    cvt_kernel<<<(nw8 + 255) / 256, 256>>>((const float4*)w3, (uint4*)gw3, nw8);
    cvt_kernel<<<(nw8 + 255) / 256, 256>>>((const float4*)w2, (uint4*)gw2, nw8);

    gemm1_mm<<<dim3(HDIM / 64, MAX_MT), 128, GSMEM>>>();
    gemm2_mm<<<dim3(DDIM / 128, MAX_MT), 128, GSMEM>>>();
    combine_kernel<<<(NTOK * (DDIM / 4) + 255) / 256, 256>>>(out);
    finalize_kernel<<<1, 32>>>(out, out_size);
}

// round 13
// speedup vs baseline: 1.3218x; 1.3218x over previous
#include <cuda_runtime.h>
#include <cuda_fp16.h>
#include <cstdint>

// ---------------- problem constants ----------------
#define NTOK   16384
#define DDIM   512
#define HDIM   1408
#define NEXP   8
#define KTOP   2
#define NPAIR  (NTOK*KTOP)
#define MTILE  128
#define MAX_MT 264

// ---------------- device scratch ----------------
__device__ __half g_xh [(size_t)NTOK * DDIM];
__device__ __half g_w1h[(size_t)NEXP * HDIM * DDIM];
__device__ __half g_w3h[(size_t)NEXP * HDIM * DDIM];
__device__ __half g_w2h[(size_t)NEXP * DDIM * HDIM];
__device__ __half g_h  [(size_t)NPAIR * HDIM];
__device__ int    g_tok_of_pair[NPAIR];
__device__ float  g_wt_of_pair[NPAIR];
__device__ int    g_exp_of_tok[NTOK * KTOP];
__device__ float  g_wt_of_tok[NTOK * KTOP];
__device__ int    g_counts[NEXP];
__device__ int    g_cursor[NEXP];
__device__ int    g_offsets[NEXP + 1];
__device__ float  g_usage[NEXP];
__device__ int    g_tile_expert[MAX_MT];
__device__ int    g_tile_row[MAX_MT];
__device__ int    g_ntiles;

// ---------------- helpers ----------------
__device__ __forceinline__ uint32_t smem_u32(const void* p) {
    uint32_t a;
    asm("{ .reg .u64 t; cvta.to.shared.u64 t, %1; cvt.u32.u64 %0, t; }" : "=r"(a) : "l"(p));
    return a;
}
__device__ __forceinline__ void cp16(uint32_t dst, const void* src) {
    asm volatile("cp.async.cg.shared.global [%0], [%1], 16;" :: "r"(dst), "l"(src));
}
#define CP_COMMIT() asm volatile("cp.async.commit_group;" ::: "memory")
#define CP_WAIT1()  asm volatile("cp.async.wait_group 1;" ::: "memory")
#define SWZ(x) ((x) ^ (((x) >> 3) & 0x70))

#define LDSM4(r0, r1, r2, r3, addr) \
    asm volatile("ldmatrix.sync.aligned.m8n8.x4.shared.b16 {%0,%1,%2,%3}, [%4];" \
        : "=r"(r0), "=r"(r1), "=r"(r2), "=r"(r3) : "r"(addr))

__device__ __forceinline__ void mma_f16(float* c, const uint32_t* a, const uint32_t* b) {
    asm volatile(
        "mma.sync.aligned.m16n8k16.row.col.f32.f16.f16.f32 "
        "{%0,%1,%2,%3}, {%4,%5,%6,%7}, {%8,%9}, {%0,%1,%2,%3};\n"
        : "+f"(c[0]), "+f"(c[1]), "+f"(c[2]), "+f"(c[3])
        : "r"(a[0]), "r"(a[1]), "r"(a[2]), "r"(a[3]), "r"(b[0]), "r"(b[1]));
}

__device__ __forceinline__ void red_add_f32(float* addr, float v) {
    asm volatile("red.global.add.f32 [%0], %1;" :: "l"(addr), "f"(v) : "memory");
}

// ---------------- small kernels (verified) ----------------
__global__ void init_kernel() {
    int i = threadIdx.x;
    if (i < NEXP) { g_counts[i] = 0; g_cursor[i] = 0; g_usage[i] = 0.f; }
}

__global__ void zero_out_kernel(float4* __restrict__ out) {
    int i = blockIdx.x * blockDim.x + threadIdx.x;
    if (i < NTOK * DDIM / 4) out[i] = make_float4(0.f, 0.f, 0.f, 0.f);
}

__global__ void __launch_bounds__(256) router_kernel(const float* __restrict__ x,
                                                     const float* __restrict__ rw) {
    int warp = threadIdx.x >> 5, lane = threadIdx.x & 31;
    int tok = blockIdx.x * 8 + warp;
    if (tok >= NTOK) return;
    const float* xr = x + (size_t)tok * DDIM;
    float xv[16];
#pragma unroll
    for (int i = 0; i < 16; i++) xv[i] = xr[lane + 32 * i];
    float logits[NEXP];
#pragma unroll
    for (int e = 0; e < NEXP; e++) {
        const float* wr = rw + e * DDIM;
        float s = 0.f;
#pragma unroll
        for (int i = 0; i < 16; i++) s += xv[i] * wr[lane + 32 * i];
#pragma unroll
        for (int o = 16; o > 0; o >>= 1) s += __shfl_xor_sync(0xffffffffu, s, o);
        logits[e] = s;
    }
    if (lane == 0) {
        float m = logits[0];
#pragma unroll
        for (int e = 1; e < NEXP; e++) m = fmaxf(m, logits[e]);
        float p[NEXP], Z = 0.f;
#pragma unroll
        for (int e = 0; e < NEXP; e++) { p[e] = __expf(logits[e] - m); Z += p[e]; }
        float inv = 1.f / Z;
        int a = 0;
#pragma unroll
        for (int e = 1; e < NEXP; e++) if (p[e] > p[a]) a = e;
        int b = (a == 0) ? 1 : 0;
#pragma unroll
        for (int e = 0; e < NEXP; e++) { if (e == a) continue; if (p[e] > p[b]) b = e; }
        float pa = p[a] * inv, pb = p[b] * inv, ws = pa + pb;
        g_exp_of_tok[tok * 2 + 0] = a;
        g_exp_of_tok[tok * 2 + 1] = b;
        g_wt_of_tok[tok * 2 + 0] = pa / ws;
        g_wt_of_tok[tok * 2 + 1] = pb / ws;
        atomicAdd(&g_counts[a], 1);
        atomicAdd(&g_counts[b], 1);
#pragma unroll
        for (int e = 0; e < NEXP; e++) atomicAdd(&g_usage[e], p[e] * inv);
    }
}

__global__ void scan_kernel() {
    if (threadIdx.x != 0) return;
    int off = 0;
    for (int e = 0; e < NEXP; e++) { g_offsets[e] = off; off += g_counts[e]; }
    g_offsets[NEXP] = off;
    int nt = 0;
    for (int e = 0; e < NEXP; e++) {
        int cnt = g_counts[e];
        for (int r = 0; r < cnt; r += MTILE) {
            g_tile_expert[nt] = e;
            g_tile_row[nt] = g_offsets[e] + r;
            nt++;
        }
    }
    g_ntiles = nt;
}

__global__ void build_kernel() {
    int i = blockIdx.x * blockDim.x + threadIdx.x;
    if (i >= NTOK * KTOP) return;
    int e = g_exp_of_tok[i];
    int pos = g_offsets[e] + atomicAdd(&g_cursor[e], 1);
    g_tok_of_pair[pos] = i >> 1;
    g_wt_of_pair[pos] = g_wt_of_tok[i];
}

__global__ void cvt_kernel(const float4* __restrict__ src, uint4* __restrict__ dst, int n8) {
    int i = blockIdx.x * blockDim.x + threadIdx.x;
    if (i >= n8) return;
    float4 s0 = src[2 * i], s1 = src[2 * i + 1];
    __half2 h0 = __floats2half2_rn(s0.x, s0.y);
    __half2 h1 = __floats2half2_rn(s0.z, s0.w);
    __half2 h2 = __floats2half2_rn(s1.x, s1.y);
    __half2 h3 = __floats2half2_rn(s1.z, s1.w);
    uint4 o;
    o.x = *(uint32_t*)&h0; o.y = *(uint32_t*)&h1;
    o.z = *(uint32_t*)&h2; o.w = *(uint32_t*)&h3;
    dst[i] = o;
}

// ============================================================
// GEMM config (R9-proven): CTA 128M, BK=64 fp16, 3-stage cp.async,
// SW128 swizzle, ldmatrix b16, m16n8k16; 256 thr, 2 CTAs/SM.
// ============================================================
#define BK        64
#define NSTG      3
#define STG_BYTES 32768
#define BOFF      16384
#define GSMEM     (NSTG * STG_BYTES)

// ---------------- GEMM1: h = silu(x@w1^T)*(x@w3^T) ----------------
// CTA 128M x 64N per matrix; 8 warps 4(M) x 2(N); warp 32x32 dual.
__global__ void __launch_bounds__(256, 2) gemm1_mm() {
    extern __shared__ char smem[];
    int mt = blockIdx.y;
    if (mt >= g_ntiles) return;
    int e = g_tile_expert[mt];
    int row0 = g_tile_row[mt];
    int valid = g_offsets[e + 1] - row0; if (valid > MTILE) valid = MTILE;
    int n0 = blockIdx.x * 64;

    uint32_t sb = smem_u32(smem);
    int tid = threadIdx.x;

    int lr = tid >> 1, half = tid & 1;
    int aidx = row0 + lr; if (aidx >= NPAIR) aidx = NPAIR - 1;
    const __half* asrc = g_xh + (size_t)g_tok_of_pair[aidx] * DDIM + half * 32;
    const __half* bsrc = (lr < 64)
        ? g_w1h + (size_t)e * HDIM * DDIM + (size_t)(n0 + lr) * DDIM + half * 32
        : g_w3h + (size_t)e * HDIM * DDIM + (size_t)(n0 + lr - 64) * DDIM + half * 32;
    uint32_t abase = lr * 128 + half * 64;

#define G1_LD(kc, st) do { \
    uint32_t _s = sb + (st) * STG_BYTES; \
    const __half* _a = asrc + (kc) * BK; \
    const __half* _b = bsrc + (kc) * BK; \
    _Pragma("unroll") for (int c = 0; c < 4; c++) { \
        cp16(_s + SWZ(abase + c * 16), _a + c * 8); \
        cp16(_s + BOFF + SWZ(abase + c * 16), _b + c * 8); \
    } \
    CP_COMMIT(); \
} while (0)

    int w = tid >> 5, lane = tid & 31;
    int wm = (w & 3) * 32, wn = (w >> 2) * 32;
    int l7 = lane & 7;
    int rA = l7 + ((lane >> 3) & 1) * 8;
    int cA = ((lane >> 4) & 1) * 16;
    int rB = l7 + ((lane >> 4) & 1) * 8;
    int cB = ((lane >> 3) & 1) * 16;
    int gid = lane >> 2, tig = lane & 3;

    float acc1[2][4][4] = {}, acc3[2][4][4] = {};

    G1_LD(0, 0);
    G1_LD(1, 1);
    const int NC = DDIM / BK;   // 8
    for (int kc = 0; kc < NC; kc++) {
        int st = kc % NSTG;
        CP_WAIT1();
        __syncthreads();
        if (kc + 2 < NC) G1_LD(kc + 2, (kc + 2) % NSTG); else CP_COMMIT();

        uint32_t sA = sb + st * STG_BYTES;
        uint32_t sB = sA + BOFF;
#pragma unroll
        for (int kk = 0; kk < 4; kk++) {
            uint32_t a[2][4];
#pragma unroll
            for (int m = 0; m < 2; m++)
                LDSM4(a[m][0], a[m][1], a[m][2], a[m][3],
                      sA + SWZ((wm + m * 16 + rA) * 128 + kk * 32 + cA));
            uint32_t b1[2][4], b3[2][4];
#pragma unroll
            for (int np = 0; np < 2; np++) {
                LDSM4(b1[np][0], b1[np][1], b1[np][2], b1[np][3],
                      sB + SWZ((wn + np * 16 + rB) * 128 + kk * 32 + cB));
                LDSM4(b3[np][0], b3[np][1], b3[np][2], b3[np][3],
                      sB + SWZ((64 + wn + np * 16 + rB) * 128 + kk * 32 + cB));
            }
#pragma unroll
            for (int m = 0; m < 2; m++)
#pragma unroll
                for (int np = 0; np < 2; np++)
#pragma unroll
                    for (int j = 0; j < 2; j++) {
                        mma_f16(acc1[m][np * 2 + j], a[m], &b1[np][j * 2]);
                        mma_f16(acc3[m][np * 2 + j], a[m], &b3[np][j * 2]);
                    }
        }
    }

#pragma unroll
    for (int m = 0; m < 2; m++)
#pragma unroll
        for (int no = 0; no < 4; no++) {
            int col = n0 + wn + no * 8 + 2 * tig;
#pragma unroll
            for (int hf = 0; hf < 2; hf++) {
                int r = wm + m * 16 + gid + hf * 8;
                if (r < valid) {
                    float z0 = acc1[m][no][hf * 2 + 0];
                    float z1 = acc1[m][no][hf * 2 + 1];
                    float s0 = z0 / (1.f + __expf(-z0));
                    float s1 = z1 / (1.f + __expf(-z1));
                    __half2 v = __floats2half2_rn(s0 * acc3[m][no][hf * 2 + 0],
                                                  s1 * acc3[m][no][hf * 2 + 1]);
                    *(__half2*)(g_h + (size_t)(row0 + r) * HDIM + col) = v;
                }
            }
        }
}

// ---------------- GEMM2: out[tok] += wt * (h @ w2^T) ----------------
// CTA 128M x 128N; 8 warps 4(M) x 2(N); warp 32x64; K=1408.
// Epilogue scatters weighted contributions via red.global.add.f32.
__global__ void __launch_bounds__(256, 2) gemm2_mm(float* __restrict__ out) {
    extern __shared__ char smem[];
    int mt = blockIdx.y;
    if (mt >= g_ntiles) return;
    int e = g_tile_expert[mt];
    int row0 = g_tile_row[mt];
    int valid = g_offsets[e + 1] - row0; if (valid > MTILE) valid = MTILE;
    int n0 = blockIdx.x * 128;

    uint32_t sb = smem_u32(smem);
    int tid = threadIdx.x;

    int lr = tid >> 1, half = tid & 1;
    int aidx = row0 + lr; if (aidx >= NPAIR) aidx = NPAIR - 1;
    const __half* asrc = g_h + (size_t)aidx * HDIM + half * 32;
    const __half* bsrc = g_w2h + (size_t)e * DDIM * HDIM + (size_t)(n0 + lr) * HDIM + half * 32;
    uint32_t abase = lr * 128 + half * 64;

#define G2_LD(kc, st) do { \
    uint32_t _s = sb + (st) * STG_BYTES; \
    const __half* _a = asrc + (kc) * BK; \
    const __half* _b = bsrc + (kc) * BK; \
    _Pragma("unroll") for (int c = 0; c < 4; c++) { \
        cp16(_s + SWZ(abase + c * 16), _a + c * 8); \
        cp16(_s + BOFF + SWZ(abase + c * 16), _b + c * 8); \
    } \
    CP_COMMIT(); \
} while (0)

    int w = tid >> 5, lane = tid & 31;
    int wm = (w & 3) * 32, wn = (w >> 2) * 64;
    int l7 = lane & 7;
    int rA = l7 + ((lane >> 3) & 1) * 8;
    int cA = ((lane >> 4) & 1) * 16;
    int rB = l7 + ((lane >> 4) & 1) * 8;
    int cB = ((lane >> 3) & 1) * 16;
    int gid = lane >> 2, tig = lane & 3;

    float acc[2][8][4] = {};

    G2_LD(0, 0);
    G2_LD(1, 1);
    const int NC = HDIM / BK;   // 22
    for (int kc = 0; kc < NC; kc++) {
        int st = kc % NSTG;
        CP_WAIT1();
        __syncthreads();
        if (kc + 2 < NC) G2_LD(kc + 2, (kc + 2) % NSTG); else CP_COMMIT();

        uint32_t sA = sb + st * STG_BYTES;
        uint32_t sB = sA + BOFF;
#pragma unroll
        for (int kk = 0; kk < 4; kk++) {
            uint32_t a[2][4];
#pragma unroll
            for (int m = 0; m < 2; m++)
                LDSM4(a[m][0], a[m][1], a[m][2], a[m][3],
                      sA + SWZ((wm + m * 16 + rA) * 128 + kk * 32 + cA));
            uint32_t b[4][4];
#pragma unroll
            for (int np = 0; np < 4; np++)
                LDSM4(b[np][0], b[np][1], b[np][2], b[np][3],
                      sB + SWZ((wn + np * 16 + rB) * 128 + kk * 32 + cB));
#pragma unroll
            for (int m = 0; m < 2; m++)
#pragma unroll
                for (int np = 0; np < 4; np++)
#pragma unroll
                    for (int j = 0; j < 2; j++)
                        mma_f16(acc[m][np * 2 + j], a[m], &b[np][j * 2]);
        }
    }

    // fused combine: out[tok*DDIM + col] += wt * acc
#pragma unroll
    for (int m = 0; m < 2; m++)
#pragma unroll
        for (int hf = 0; hf < 2; hf++) {
            int r = wm + m * 16 + gid + hf * 8;
            if (r < valid) {
                int tok = g_tok_of_pair[row0 + r];
                float wt = g_wt_of_pair[row0 + r];
                float* op = out + (size_t)tok * DDIM + n0 + wn + 2 * tig;
#pragma unroll
                for (int no = 0; no < 8; no++) {
                    red_add_f32(op + no * 8 + 0, wt * acc[m][no][hf * 2 + 0]);
                    red_add_f32(op + no * 8 + 1, wt * acc[m][no][hf * 2 + 1]);
                }
            }
        }
}

// ---------------- aux ----------------
__global__ void finalize_kernel(float* __restrict__ out, int out_size) {
    if (threadIdx.x != 0 || blockIdx.x != 0) return;
    if (out_size > NTOK * DDIM) {
        float s = 0.f;
        for (int e = 0; e < NEXP; e++) {
            float u = g_usage[e] / (float)NTOK;
            s += u * u;
        }
        out[NTOK * DDIM] = (float)NEXP * 0.01f * s;
    }
}

// ---------------- launch ----------------
extern "C" void kernel_launch(void* const* d_in, const int* in_sizes, int n_in,
                              void* d_out, int out_size) {
    const float* x  = (const float*)d_in[0];
    const float* rw = (const float*)d_in[1];
    const float* w1 = (const float*)d_in[2];
    const float* w2 = (const float*)d_in[3];
    const float* w3 = (const float*)d_in[4];
    float* out = (float*)d_out;

    cudaFuncSetAttribute(gemm1_mm, cudaFuncAttributeMaxDynamicSharedMemorySize, GSMEM);
    cudaFuncSetAttribute(gemm2_mm, cudaFuncAttributeMaxDynamicSharedMemorySize, GSMEM);

    __half* gxh;  cudaGetSymbolAddress((void**)&gxh,  g_xh);
    __half* gw1;  cudaGetSymbolAddress((void**)&gw1,  g_w1h);
    __half* gw3;  cudaGetSymbolAddress((void**)&gw3,  g_w3h);
    __half* gw2;  cudaGetSymbolAddress((void**)&gw2,  g_w2h);

    init_kernel<<<1, 32>>>();
    zero_out_kernel<<<(NTOK * DDIM / 4 + 255) / 256, 256>>>((float4*)out);
    router_kernel<<<NTOK / 8, 256>>>(x, rw);
    scan_kernel<<<1, 32>>>();
    build_kernel<<<(NTOK * KTOP + 255) / 256, 256>>>();

    int nx8 = NTOK * DDIM / 8, nw8 = NEXP * HDIM * DDIM / 8;
    cvt_kernel<<<(nx8 + 255) / 256, 256>>>((const float4*)x,  (uint4*)gxh, nx8);
    cvt_kernel<<<(nw8 + 255) / 256, 256>>>((const float4*)w1, (uint4*)gw1, nw8);
    cvt_kernel<<<(nw8 + 255) / 256, 256>>>((const float4*)w3, (uint4*)gw3, nw8);
    cvt_kernel<<<(nw8 + 255) / 256, 256>>>((const float4*)w2, (uint4*)gw2, nw8);

    gemm1_mm<<<dim3(HDIM / 64, MAX_MT), 256, GSMEM>>>();
    gemm2_mm<<<dim3(DDIM / 128, MAX_MT), 256, GSMEM>>>(out);
    finalize_kernel<<<1, 32>>>(out, out_size);
}

// round 14
// speedup vs baseline: 1.4618x; 1.1059x over previous
#include <cuda_runtime.h>
#include <cuda_fp16.h>
#include <cstdint>

// ---------------- problem constants ----------------
#define NTOK   16384
#define DDIM   512
#define HDIM   1408
#define NEXP   8
#define KTOP   2
#define NPAIR  (NTOK*KTOP)
#define MTILE  128
#define MAX_MT 264

// ---------------- device scratch ----------------
__device__ __half g_xh [(size_t)NTOK * DDIM];
__device__ __half g_w1h[(size_t)NEXP * HDIM * DDIM];
__device__ __half g_w3h[(size_t)NEXP * HDIM * DDIM];
__device__ __half g_w2h[(size_t)NEXP * DDIM * HDIM];
__device__ __half g_h  [(size_t)NPAIR * HDIM];
__device__ float  g_probs[(size_t)NTOK * NEXP];
__device__ int    g_tok_of_pair[NPAIR];
__device__ float  g_wt_of_pair[NPAIR];
__device__ int    g_exp_of_tok[NTOK * KTOP];
__device__ float  g_wt_of_tok[NTOK * KTOP];
__device__ int    g_cursor[NEXP];
__device__ int    g_offsets[NEXP + 1];
__device__ float  g_usage[NEXP];
__device__ int    g_tile_expert[MAX_MT];
__device__ int    g_tile_row[MAX_MT];
__device__ int    g_ntiles;

// ---------------- helpers ----------------
__device__ __forceinline__ uint32_t smem_u32(const void* p) {
    uint32_t a;
    asm("{ .reg .u64 t; cvta.to.shared.u64 t, %1; cvt.u32.u64 %0, t; }" : "=r"(a) : "l"(p));
    return a;
}
__device__ __forceinline__ void cp16(uint32_t dst, const void* src) {
    asm volatile("cp.async.cg.shared.global [%0], [%1], 16;" :: "r"(dst), "l"(src));
}
#define CP_COMMIT() asm volatile("cp.async.commit_group;" ::: "memory")
#define CP_WAIT1()  asm volatile("cp.async.wait_group 1;" ::: "memory")
#define SWZ(x) ((x) ^ (((x) >> 3) & 0x70))

#define LDSM4(r0, r1, r2, r3, addr) \
    asm volatile("ldmatrix.sync.aligned.m8n8.x4.shared.b16 {%0,%1,%2,%3}, [%4];" \
        : "=r"(r0), "=r"(r1), "=r"(r2), "=r"(r3) : "r"(addr))

__device__ __forceinline__ void mma_f16(float* c, const uint32_t* a, const uint32_t* b) {
    asm volatile(
        "mma.sync.aligned.m16n8k16.row.col.f32.f16.f16.f32 "
        "{%0,%1,%2,%3}, {%4,%5,%6,%7}, {%8,%9}, {%0,%1,%2,%3};\n"
        : "+f"(c[0]), "+f"(c[1]), "+f"(c[2]), "+f"(c[3])
        : "r"(a[0]), "r"(a[1]), "r"(a[2]), "r"(a[3]), "r"(b[0]), "r"(b[1]));
}

__device__ __forceinline__ void red_add_f32(float* addr, float v) {
    asm volatile("red.global.add.f32 [%0], %1;" :: "l"(addr), "f"(v) : "memory");
}

// ---------------- launch 1: router (no atomics, no init needed) ----------------
__global__ void __launch_bounds__(256) router_kernel(const float* __restrict__ x,
                                                     const float* __restrict__ rw) {
    int warp = threadIdx.x >> 5, lane = threadIdx.x & 31;
    int tok = blockIdx.x * 8 + warp;
    if (tok >= NTOK) return;
    const float* xr = x + (size_t)tok * DDIM;
    float xv[16];
#pragma unroll
    for (int i = 0; i < 16; i++) xv[i] = xr[lane + 32 * i];
    float logits[NEXP];
#pragma unroll
    for (int e = 0; e < NEXP; e++) {
        const float* wr = rw + e * DDIM;
        float s = 0.f;
#pragma unroll
        for (int i = 0; i < 16; i++) s += xv[i] * wr[lane + 32 * i];
#pragma unroll
        for (int o = 16; o > 0; o >>= 1) s += __shfl_xor_sync(0xffffffffu, s, o);
        logits[e] = s;
    }
    if (lane == 0) {
        float m = logits[0];
#pragma unroll
        for (int e = 1; e < NEXP; e++) m = fmaxf(m, logits[e]);
        float p[NEXP], Z = 0.f;
#pragma unroll
        for (int e = 0; e < NEXP; e++) { p[e] = __expf(logits[e] - m); Z += p[e]; }
        float inv = 1.f / Z;
        int a = 0;
#pragma unroll
        for (int e = 1; e < NEXP; e++) if (p[e] > p[a]) a = e;
        int b = (a == 0) ? 1 : 0;
#pragma unroll
        for (int e = 0; e < NEXP; e++) { if (e == a) continue; if (p[e] > p[b]) b = e; }
        float pa = p[a] * inv, pb = p[b] * inv, ws = pa + pb;
        g_exp_of_tok[tok * 2 + 0] = a;
        g_exp_of_tok[tok * 2 + 1] = b;
        g_wt_of_tok[tok * 2 + 0] = pa / ws;
        g_wt_of_tok[tok * 2 + 1] = pb / ws;
#pragma unroll
        for (int e = 0; e < NEXP; e++) g_probs[tok * NEXP + e] = p[e] * inv;
    }
}

// ---------------- launch 2: prep = counts + usage + scan + tiles + build ----------------
__global__ void __launch_bounds__(1024) prep_kernel() {
    __shared__ int s_cnt[NEXP];
    __shared__ float s_use[NEXP];
    int tid = threadIdx.x;
    if (tid < NEXP) { s_cnt[tid] = 0; s_use[tid] = 0.f; }
    __syncthreads();

    // per-thread static accumulators (unrolled compare keeps them in regs)
    int c[NEXP] = {};
    for (int i = tid; i < NTOK * KTOP; i += 1024) {
        int e = g_exp_of_tok[i];
#pragma unroll
        for (int k = 0; k < NEXP; k++) c[k] += (e == k);
    }
    float u[NEXP] = {};
    for (int t = tid; t < NTOK; t += 1024) {
#pragma unroll
        for (int k = 0; k < NEXP; k++) u[k] += g_probs[t * NEXP + k];
    }
#pragma unroll
    for (int k = 0; k < NEXP; k++) {
        atomicAdd(&s_cnt[k], c[k]);
        atomicAdd(&s_use[k], u[k]);
    }
    __syncthreads();

    if (tid == 0) {
        int off = 0;
        for (int e = 0; e < NEXP; e++) {
            g_offsets[e] = off;
            g_cursor[e] = off;
            g_usage[e] = s_use[e];
            off += s_cnt[e];
        }
        g_offsets[NEXP] = off;
        int nt = 0;
        for (int e = 0; e < NEXP; e++) {
            for (int r = 0; r < s_cnt[e]; r += MTILE) {
                g_tile_expert[nt] = e;
                g_tile_row[nt] = g_offsets[e] + r;
                nt++;
            }
        }
        g_ntiles = nt;
    }
    __syncthreads();

    // build grouped pair arrays
    for (int i = tid; i < NTOK * KTOP; i += 1024) {
        int e = g_exp_of_tok[i];
        int pos = atomicAdd(&g_cursor[e], 1);
        g_tok_of_pair[pos] = i >> 1;
        g_wt_of_pair[pos] = g_wt_of_tok[i];
    }
}

// ---------------- launch 3: fused conversions + out zeroing ----------------
__device__ __forceinline__ void cvt8(const float4* src, uint4* dst, int i) {
    float4 s0 = src[2 * i], s1 = src[2 * i + 1];
    __half2 h0 = __floats2half2_rn(s0.x, s0.y);
    __half2 h1 = __floats2half2_rn(s0.z, s0.w);
    __half2 h2 = __floats2half2_rn(s1.x, s1.y);
    __half2 h3 = __floats2half2_rn(s1.z, s1.w);
    uint4 o;
    o.x = *(uint32_t*)&h0; o.y = *(uint32_t*)&h1;
    o.z = *(uint32_t*)&h2; o.w = *(uint32_t*)&h3;
    dst[i] = o;
}

#define NX8 (NTOK * DDIM / 8)
#define NW8 (NEXP * HDIM * DDIM / 8)
#define NZ4 (NTOK * DDIM / 4)
#define CVT_TOTAL (NX8 + 3 * NW8 + NZ4)

__global__ void __launch_bounds__(256) cvt_all_kernel(const float4* __restrict__ x,
                                                      const float4* __restrict__ w1,
                                                      const float4* __restrict__ w2,
                                                      const float4* __restrict__ w3,
                                                      float4* __restrict__ out) {
    int i = blockIdx.x * blockDim.x + threadIdx.x;
    if (i < NX8) {
        cvt8(x, (uint4*)g_xh, i);
    } else if (i < NX8 + NW8) {
        cvt8(w1, (uint4*)g_w1h, i - NX8);
    } else if (i < NX8 + 2 * NW8) {
        cvt8(w3, (uint4*)g_w3h, i - NX8 - NW8);
    } else if (i < NX8 + 3 * NW8) {
        cvt8(w2, (uint4*)g_w2h, i - NX8 - 2 * NW8);
    } else if (i < CVT_TOTAL) {
        out[i - NX8 - 3 * NW8] = make_float4(0.f, 0.f, 0.f, 0.f);
    }
}

// ============================================================
// GEMM config (R9-proven): CTA 128M, BK=64 fp16, 3-stage cp.async,
// SW128 swizzle, ldmatrix b16, m16n8k16; 256 thr, 2 CTAs/SM.
// ============================================================
#define BK        64
#define NSTG      3
#define STG_BYTES 32768
#define BOFF      16384
#define GSMEM     (NSTG * STG_BYTES)

// ---------------- launch 4 (PROFILED): GEMM1 h = silu(x@w1^T)*(x@w3^T) ----------------
__global__ void __launch_bounds__(256, 2) gemm1_mm() {
    extern __shared__ char smem[];
    int mt = blockIdx.y;
    if (mt >= g_ntiles) return;
    int e = g_tile_expert[mt];
    int row0 = g_tile_row[mt];
    int valid = g_offsets[e + 1] - row0; if (valid > MTILE) valid = MTILE;
    int n0 = blockIdx.x * 64;

    uint32_t sb = smem_u32(smem);
    int tid = threadIdx.x;

    int lr = tid >> 1, half = tid & 1;
    int aidx = row0 + lr; if (aidx >= NPAIR) aidx = NPAIR - 1;
    const __half* asrc = g_xh + (size_t)g_tok_of_pair[aidx] * DDIM + half * 32;
    const __half* bsrc = (lr < 64)
        ? g_w1h + (size_t)e * HDIM * DDIM + (size_t)(n0 + lr) * DDIM + half * 32
        : g_w3h + (size_t)e * HDIM * DDIM + (size_t)(n0 + lr - 64) * DDIM + half * 32;
    uint32_t abase = lr * 128 + half * 64;

#define G1_LD(kc, st) do { \
    uint32_t _s = sb + (st) * STG_BYTES; \
    const __half* _a = asrc + (kc) * BK; \
    const __half* _b = bsrc + (kc) * BK; \
    _Pragma("unroll") for (int c = 0; c < 4; c++) { \
        cp16(_s + SWZ(abase + c * 16), _a + c * 8); \
        cp16(_s + BOFF + SWZ(abase + c * 16), _b + c * 8); \
    } \
    CP_COMMIT(); \
} while (0)

    int w = tid >> 5, lane = tid & 31;
    int wm = (w & 3) * 32, wn = (w >> 2) * 32;
    int l7 = lane & 7;
    int rA = l7 + ((lane >> 3) & 1) * 8;
    int cA = ((lane >> 4) & 1) * 16;
    int rB = l7 + ((lane >> 4) & 1) * 8;
    int cB = ((lane >> 3) & 1) * 16;
    int gid = lane >> 2, tig = lane & 3;

    float acc1[2][4][4] = {}, acc3[2][4][4] = {};

    G1_LD(0, 0);
    G1_LD(1, 1);
    const int NC = DDIM / BK;   // 8
    for (int kc = 0; kc < NC; kc++) {
        int st = kc % NSTG;
        CP_WAIT1();
        __syncthreads();
        if (kc + 2 < NC) G1_LD(kc + 2, (kc + 2) % NSTG); else CP_COMMIT();

        uint32_t sA = sb + st * STG_BYTES;
        uint32_t sB = sA + BOFF;
#pragma unroll
        for (int kk = 0; kk < 4; kk++) {
            uint32_t a[2][4];
#pragma unroll
            for (int m = 0; m < 2; m++)
                LDSM4(a[m][0], a[m][1], a[m][2], a[m][3],
                      sA + SWZ((wm + m * 16 + rA) * 128 + kk * 32 + cA));
            uint32_t b1[2][4], b3[2][4];
#pragma unroll
            for (int np = 0; np < 2; np++) {
                LDSM4(b1[np][0], b1[np][1], b1[np][2], b1[np][3],
                      sB + SWZ((wn + np * 16 + rB) * 128 + kk * 32 + cB));
                LDSM4(b3[np][0], b3[np][1], b3[np][2], b3[np][3],
                      sB + SWZ((64 + wn + np * 16 + rB) * 128 + kk * 32 + cB));
            }
#pragma unroll
            for (int m = 0; m < 2; m++)
#pragma unroll
                for (int np = 0; np < 2; np++)
#pragma unroll
                    for (int j = 0; j < 2; j++) {
                        mma_f16(acc1[m][np * 2 + j], a[m], &b1[np][j * 2]);
                        mma_f16(acc3[m][np * 2 + j], a[m], &b3[np][j * 2]);
                    }
        }
    }

#pragma unroll
    for (int m = 0; m < 2; m++)
#pragma unroll
        for (int no = 0; no < 4; no++) {
            int col = n0 + wn + no * 8 + 2 * tig;
#pragma unroll
            for (int hf = 0; hf < 2; hf++) {
                int r = wm + m * 16 + gid + hf * 8;
                if (r < valid) {
                    float z0 = acc1[m][no][hf * 2 + 0];
                    float z1 = acc1[m][no][hf * 2 + 1];
                    float s0 = z0 / (1.f + __expf(-z0));
                    float s1 = z1 / (1.f + __expf(-z1));
                    __half2 v = __floats2half2_rn(s0 * acc3[m][no][hf * 2 + 0],
                                                  s1 * acc3[m][no][hf * 2 + 1]);
                    *(__half2*)(g_h + (size_t)(row0 + r) * HDIM + col) = v;
                }
            }
        }
}

// ---------------- launch 5: GEMM2 out[tok] += wt * (h @ w2^T) ----------------
__global__ void __launch_bounds__(256, 2) gemm2_mm(float* __restrict__ out) {
    extern __shared__ char smem[];
    int mt = blockIdx.y;
    if (mt >= g_ntiles) return;
    int e = g_tile_expert[mt];
    int row0 = g_tile_row[mt];
    int valid = g_offsets[e + 1] - row0; if (valid > MTILE) valid = MTILE;
    int n0 = blockIdx.x * 128;

    uint32_t sb = smem_u32(smem);
    int tid = threadIdx.x;

    int lr = tid >> 1, half = tid & 1;
    int aidx = row0 + lr; if (aidx >= NPAIR) aidx = NPAIR - 1;
    const __half* asrc = g_h + (size_t)aidx * HDIM + half * 32;
    const __half* bsrc = g_w2h + (size_t)e * DDIM * HDIM + (size_t)(n0 + lr) * HDIM + half * 32;
    uint32_t abase = lr * 128 + half * 64;

#define G2_LD(kc, st) do { \
    uint32_t _s = sb + (st) * STG_BYTES; \
    const __half* _a = asrc + (kc) * BK; \
    const __half* _b = bsrc + (kc) * BK; \
    _Pragma("unroll") for (int c = 0; c < 4; c++) { \
        cp16(_s + SWZ(abase + c * 16), _a + c * 8); \
        cp16(_s + BOFF + SWZ(abase + c * 16), _b + c * 8); \
    } \
    CP_COMMIT(); \
} while (0)

    int w = tid >> 5, lane = tid & 31;
    int wm = (w & 3) * 32, wn = (w >> 2) * 64;
    int l7 = lane & 7;
    int rA = l7 + ((lane >> 3) & 1) * 8;
    int cA = ((lane >> 4) & 1) * 16;
    int rB = l7 + ((lane >> 4) & 1) * 8;
    int cB = ((lane >> 3) & 1) * 16;
    int gid = lane >> 2, tig = lane & 3;

    float acc[2][8][4] = {};

    G2_LD(0, 0);
    G2_LD(1, 1);
    const int NC = HDIM / BK;   // 22
    for (int kc = 0; kc < NC; kc++) {
        int st = kc % NSTG;
        CP_WAIT1();
        __syncthreads();
        if (kc + 2 < NC) G2_LD(kc + 2, (kc + 2) % NSTG); else CP_COMMIT();

        uint32_t sA = sb + st * STG_BYTES;
        uint32_t sB = sA + BOFF;
#pragma unroll
        for (int kk = 0; kk < 4; kk++) {
            uint32_t a[2][4];
#pragma unroll
            for (int m = 0; m < 2; m++)
                LDSM4(a[m][0], a[m][1], a[m][2], a[m][3],
                      sA + SWZ((wm + m * 16 + rA) * 128 + kk * 32 + cA));
            uint32_t b[4][4];
#pragma unroll
            for (int np = 0; np < 4; np++)
                LDSM4(b[np][0], b[np][1], b[np][2], b[np][3],
                      sB + SWZ((wn + np * 16 + rB) * 128 + kk * 32 + cB));
#pragma unroll
            for (int m = 0; m < 2; m++)
#pragma unroll
                for (int np = 0; np < 4; np++)
#pragma unroll
                    for (int j = 0; j < 2; j++)
                        mma_f16(acc[m][np * 2 + j], a[m], &b[np][j * 2]);
        }
    }

    // fused combine: out[tok*DDIM + col] += wt * acc
#pragma unroll
    for (int m = 0; m < 2; m++)
#pragma unroll
        for (int hf = 0; hf < 2; hf++) {
            int r = wm + m * 16 + gid + hf * 8;
            if (r < valid) {
                int tok = g_tok_of_pair[row0 + r];
                float wt = g_wt_of_pair[row0 + r];
                float* op = out + (size_t)tok * DDIM + n0 + wn + 2 * tig;
#pragma unroll
                for (int no = 0; no < 8; no++) {
                    red_add_f32(op + no * 8 + 0, wt * acc[m][no][hf * 2 + 0]);
                    red_add_f32(op + no * 8 + 1, wt * acc[m][no][hf * 2 + 1]);
                }
            }
        }
}

// ---------------- launch 6: aux loss ----------------
__global__ void finalize_kernel(float* __restrict__ out, int out_size) {
    if (threadIdx.x != 0 || blockIdx.x != 0) return;
    if (out_size > NTOK * DDIM) {
        float s = 0.f;
        for (int e = 0; e < NEXP; e++) {
            float u = g_usage[e] / (float)NTOK;
            s += u * u;
        }
        out[NTOK * DDIM] = (float)NEXP * 0.01f * s;
    }
}

// ---------------- launch ----------------
extern "C" void kernel_launch(void* const* d_in, const int* in_sizes, int n_in,
                              void* d_out, int out_size) {
    const float* x  = (const float*)d_in[0];
    const float* rw = (const float*)d_in[1];
    const float* w1 = (const float*)d_in[2];
    const float* w2 = (const float*)d_in[3];
    const float* w3 = (const float*)d_in[4];
    float* out = (float*)d_out;

    cudaFuncSetAttribute(gemm1_mm, cudaFuncAttributeMaxDynamicSharedMemorySize, GSMEM);
    cudaFuncSetAttribute(gemm2_mm, cudaFuncAttributeMaxDynamicSharedMemorySize, GSMEM);

    router_kernel<<<NTOK / 8, 256>>>(x, rw);
    prep_kernel<<<1, 1024>>>();
    cvt_all_kernel<<<(CVT_TOTAL + 255) / 256, 256>>>(
        (const float4*)x, (const float4*)w1, (const float4*)w2, (const float4*)w3,
        (float4*)out);
    gemm1_mm<<<dim3(HDIM / 64, MAX_MT), 256, GSMEM>>>();
    gemm2_mm<<<dim3(DDIM / 128, MAX_MT), 256, GSMEM>>>(out);
    finalize_kernel<<<1, 32>>>(out, out_size);
}